// round 2
// baseline (speedup 1.0000x reference)
#include <cuda_runtime.h>

// PixelWiseRNN: h_t = tanh(w_ih*x_t + b_ih + w_hh*h_{t-1} + b_hh), h_0 = 0
// x: (B, T, Z, H, W) fp32, params: (Z, H, W) fp32, out: (B, T, Z, H, W) fp32
// B=4, T=256, Z=16, H=64, W=64  ->  P = Z*H*W = 65536 pixels per batch.
//
// float4 over W (4 adjacent independent pixels per thread), depth-2 x-prefetch,
// streaming cache hints (no reuse).

#define RNN_B 4
#define RNN_T 256
#define RNN_P 65536          // Z*H*W
#define RNN_NV (RNN_P / 4)   // 16384 float4 vectors per batch slice

__global__ __launch_bounds__(64) void pixel_rnn_kernel(
    const float* __restrict__ x,
    const float* __restrict__ w_ih,
    const float* __restrict__ w_hh,
    const float* __restrict__ b_ih,
    const float* __restrict__ b_hh,
    float* __restrict__ out)
{
    const int gid = blockIdx.x * blockDim.x + threadIdx.x;  // [0, B*NV) = 65536
    const int b = gid >> 14;            // gid / NV
    const int v = gid & (RNN_NV - 1);   // gid % NV
    const int p = v << 2;               // first of 4 adjacent pixels

    const float4 wi = *(const float4*)(w_ih + p);
    const float4 wh = *(const float4*)(w_hh + p);
    const float4 bi = *(const float4*)(b_ih + p);
    const float4 bh = *(const float4*)(b_hh + p);
    const float4 bias = make_float4(bi.x + bh.x, bi.y + bh.y,
                                    bi.z + bh.z, bi.w + bh.w);

    const size_t base = (size_t)b * RNN_T * RNN_P + p;
    const float4* __restrict__ xp = (const float4*)(x + base);
    float4* __restrict__ op = (float4*)(out + base);
    // per-timestep stride in float4 units:
    const int stride = RNN_P / 4;       // 16384

    float4 h = make_float4(0.f, 0.f, 0.f, 0.f);

    // Software pipeline: keep 2 x-vectors in flight.
    float4 x0 = __ldcs(xp);
    float4 x1 = __ldcs(xp + stride);

    #pragma unroll 4
    for (int t = 0; t < RNN_T; t++) {
        // Prefetch x[t+2] (clamped); lands while we do this step's math.
        const int tn = (t + 2 < RNN_T) ? (t + 2) : (RNN_T - 1);
        const float4 xn = __ldcs(xp + (size_t)tn * stride);

        // Off-chain: a = wi*x + bias (independent of h).
        const float ax = fmaf(wi.x, x0.x, bias.x);
        const float ay = fmaf(wi.y, x0.y, bias.y);
        const float az = fmaf(wi.z, x0.z, bias.z);
        const float aw = fmaf(wi.w, x0.w, bias.w);

        h.x = tanhf(fmaf(wh.x, h.x, ax));
        h.y = tanhf(fmaf(wh.y, h.y, ay));
        h.z = tanhf(fmaf(wh.z, h.z, az));
        h.w = tanhf(fmaf(wh.w, h.w, aw));

        __stcs(op + (size_t)t * stride, h);

        x0 = x1;
        x1 = xn;
    }
}

extern "C" void kernel_launch(void* const* d_in, const int* in_sizes, int n_in,
                              void* d_out, int out_size)
{
    const float* x    = (const float*)d_in[0];
    const float* w_ih = (const float*)d_in[1];
    const float* w_hh = (const float*)d_in[2];
    const float* b_ih = (const float*)d_in[3];
    const float* b_hh = (const float*)d_in[4];
    float* out = (float*)d_out;

    const int total_threads = RNN_B * RNN_NV;  // 65536
    const int block = 64;
    const int grid = total_threads / block;    // 1024

    pixel_rnn_kernel<<<grid, block>>>(x, w_ih, w_hh, b_ih, b_hh, out);
}

// round 3
// speedup vs baseline: 1.0328x; 1.0328x over previous
#include <cuda_runtime.h>

// PixelWiseRNN: h_t = tanh(w_ih*x_t + b_ih + w_hh*h_{t-1} + b_hh), h_0 = 0
// x: (B, T, Z, H, W) fp32, params: (Z, H, W) fp32, out: (B, T, Z, H, W) fp32
// B=4, T=256, Z=16, H=64, W=64  ->  P = Z*H*W = 65536 pixels per batch.
//
// One scalar pixel chain per thread (262144 threads -> high occupancy, which
// is the latency-hiding resource here). Depth-2 prefetch of x keeps two loads
// in flight per thread; streaming hints avoid L2 pollution.

#define RNN_B 4
#define RNN_T 256
#define RNN_P 65536   // Z*H*W

__global__ __launch_bounds__(256) void pixel_rnn_kernel(
    const float* __restrict__ x,
    const float* __restrict__ w_ih,
    const float* __restrict__ w_hh,
    const float* __restrict__ b_ih,
    const float* __restrict__ b_hh,
    float* __restrict__ out)
{
    const int gid = blockIdx.x * blockDim.x + threadIdx.x;   // [0, B*P)
    const int b = gid >> 16;          // gid / P
    const int p = gid & (RNN_P - 1);  // gid % P

    const float wi   = w_ih[p];
    const float wh   = w_hh[p];
    const float bias = b_ih[p] + b_hh[p];

    const size_t base = (size_t)b * RNN_T * RNN_P + p;
    const float* __restrict__ xp = x + base;
    float* __restrict__ op = out + base;

    float h = 0.0f;

    // Depth-2 software pipeline: two x loads in flight at all times.
    float x0 = __ldcs(xp);
    float x1 = __ldcs(xp + RNN_P);

    #pragma unroll 4
    for (int t = 0; t < RNN_T; t++) {
        // Prefetch x[t+2] (clamped at the tail) — lands during this step's math.
        const int tn = (t + 2 < RNN_T) ? (t + 2) : (RNN_T - 1);
        const float xn = __ldcs(xp + (size_t)tn * RNN_P);

        // Off-chain part first: a = wi*x + bias (independent of h).
        const float a = fmaf(wi, x0, bias);
        h = tanhf(fmaf(wh, h, a));

        __stcs(op + (size_t)t * RNN_P, h);

        x0 = x1;
        x1 = xn;
    }
}

extern "C" void kernel_launch(void* const* d_in, const int* in_sizes, int n_in,
                              void* d_out, int out_size)
{
    const float* x    = (const float*)d_in[0];
    const float* w_ih = (const float*)d_in[1];
    const float* w_hh = (const float*)d_in[2];
    const float* b_ih = (const float*)d_in[3];
    const float* b_hh = (const float*)d_in[4];
    float* out = (float*)d_out;

    const int total_threads = RNN_B * RNN_P;   // 262144
    const int block = 256;
    const int grid = total_threads / block;    // 1024

    pixel_rnn_kernel<<<grid, block>>>(x, w_ih, w_hh, b_ih, b_hh, out);
}

// round 4
// speedup vs baseline: 1.2754x; 1.2348x over previous
#include <cuda_runtime.h>

// PixelWiseRNN: h_t = tanh(w_ih*x_t + b_ih + w_hh*h_{t-1} + b_hh), h_0 = 0
// x: (B, T, Z, H, W) fp32, params: (Z, H, W) fp32, out: (B, T, Z, H, W) fp32
// B=4, T=256, Z=16, H=64, W=64  ->  P = Z*H*W = 65536 pixels per batch.
//
// Structure identical to the R0 baseline (scalar pixel per thread, 256/block,
// unroll-4 with t+1 prefetch -> ptxas front-batches the 4 independent LDGs).
// Only change: branch-free fast tanh (EX2 + RCP, 6 instr) replacing libdevice
// tanhf (~16 instr + divergent branch) to get instruction-issue demand well
// below the HBM streaming time.

#define RNN_B 4
#define RNN_T 256
#define RNN_P 65536   // Z*H*W

__device__ __forceinline__ float fast_tanh(float z)
{
    // Clamp: tanh(+-10) == +-1.0f exactly in fp32, and exp never overflows.
    z = fminf(fmaxf(z, -10.0f), 10.0f);
    const float t = __expf(2.0f * z);            // FMUL + MUFU.EX2
    return __fdividef(t - 1.0f, t + 1.0f);       // FADD, FADD, MUFU.RCP, FMUL
}

__global__ __launch_bounds__(256) void pixel_rnn_kernel(
    const float* __restrict__ x,
    const float* __restrict__ w_ih,
    const float* __restrict__ w_hh,
    const float* __restrict__ b_ih,
    const float* __restrict__ b_hh,
    float* __restrict__ out)
{
    const int gid = blockIdx.x * blockDim.x + threadIdx.x;   // [0, B*P)
    const int b = gid >> 16;          // gid / P
    const int p = gid & (RNN_P - 1);  // gid % P

    const float wi   = w_ih[p];
    const float wh   = w_hh[p];
    const float bias = b_ih[p] + b_hh[p];

    const size_t base = (size_t)b * RNN_T * RNN_P + p;
    const float* __restrict__ xp = x + base;
    float* __restrict__ op = out + base;

    float h  = 0.0f;
    float xv = xp[0];   // prefetched x_0

    #pragma unroll 4
    for (int t = 0; t < RNN_T; t++) {
        // Prefetch next x off the dependency chain (clamped at the end).
        const int tn = (t + 1 < RNN_T) ? (t + 1) : t;
        const float xn = xp[(size_t)tn * RNN_P];

        // Off-chain part first: a = wi*x + bias (independent of h).
        const float a = fmaf(wi, xv, bias);
        h = fast_tanh(fmaf(wh, h, a));

        op[(size_t)t * RNN_P] = h;
        xv = xn;
    }
}

extern "C" void kernel_launch(void* const* d_in, const int* in_sizes, int n_in,
                              void* d_out, int out_size)
{
    const float* x    = (const float*)d_in[0];
    const float* w_ih = (const float*)d_in[1];
    const float* w_hh = (const float*)d_in[2];
    const float* b_ih = (const float*)d_in[3];
    const float* b_hh = (const float*)d_in[4];
    float* out = (float*)d_out;

    const int total_threads = RNN_B * RNN_P;   // 262144
    const int block = 256;
    const int grid = total_threads / block;    // 1024

    pixel_rnn_kernel<<<grid, block>>>(x, w_ih, w_hh, b_ih, b_hh, out);
}

// round 5
// speedup vs baseline: 1.3071x; 1.0248x over previous
#include <cuda_runtime.h>

// PixelWiseRNN: h_t = tanh(w_ih*x_t + b_ih + w_hh*h_{t-1} + b_hh), h_0 = 0
// x: (B, T, Z, H, W) fp32, params: (Z, H, W) fp32, out: (B, T, Z, H, W) fp32
// B=4, T=256, Z=16, H=64, W=64  ->  P = Z*H*W = 65536 pixels per batch.
//
// Latency-chain-bound kernel (R3 post-mortem: issue was NOT the limiter).
// This round: hardware tanh (MUFU.TANH via tanh.approx.f32, sm_75+) shrinks
// the per-step serial dependency chain from ~50 cyc (EX2+RCP sequence) to
// ~24 cyc (FFMA+FFMA+MUFU.TANH), halving the per-body chain so warps return
// to their memory phase sooner. Everything else identical to the R3 kernel.

#define RNN_B 4
#define RNN_T 256
#define RNN_P 65536   // Z*H*W

__device__ __forceinline__ float hw_tanh(float z)
{
    float r;
    asm("tanh.approx.f32 %0, %1;" : "=f"(r) : "f"(z));
    return r;
}

__global__ __launch_bounds__(256) void pixel_rnn_kernel(
    const float* __restrict__ x,
    const float* __restrict__ w_ih,
    const float* __restrict__ w_hh,
    const float* __restrict__ b_ih,
    const float* __restrict__ b_hh,
    float* __restrict__ out)
{
    const int gid = blockIdx.x * blockDim.x + threadIdx.x;   // [0, B*P)
    const int b = gid >> 16;          // gid / P
    const int p = gid & (RNN_P - 1);  // gid % P

    const float wi   = w_ih[p];
    const float wh   = w_hh[p];
    const float bias = b_ih[p] + b_hh[p];

    const size_t base = (size_t)b * RNN_T * RNN_P + p;
    const float* __restrict__ xp = x + base;
    float* __restrict__ op = out + base;

    float h  = 0.0f;
    float xv = xp[0];   // prefetched x_0

    #pragma unroll 4
    for (int t = 0; t < RNN_T; t++) {
        // Prefetch next x off the dependency chain (clamped at the end).
        const int tn = (t + 1 < RNN_T) ? (t + 1) : t;
        const float xn = xp[(size_t)tn * RNN_P];

        // Off-chain part first: a = wi*x + bias (independent of h).
        const float a = fmaf(wi, xv, bias);
        h = hw_tanh(fmaf(wh, h, a));

        op[(size_t)t * RNN_P] = h;
        xv = xn;
    }
}

extern "C" void kernel_launch(void* const* d_in, const int* in_sizes, int n_in,
                              void* d_out, int out_size)
{
    const float* x    = (const float*)d_in[0];
    const float* w_ih = (const float*)d_in[1];
    const float* w_hh = (const float*)d_in[2];
    const float* b_ih = (const float*)d_in[3];
    const float* b_hh = (const float*)d_in[4];
    float* out = (float*)d_out;

    const int total_threads = RNN_B * RNN_P;   // 262144
    const int block = 256;
    const int grid = total_threads / block;    // 1024

    pixel_rnn_kernel<<<grid, block>>>(x, w_ih, w_hh, b_ih, b_hh, out);
}